// round 1
// baseline (speedup 1.0000x reference)
#include <cuda_runtime.h>
#include <cuda_bf16.h>

// Problem dims (fixed by setup_inputs)
#define N_ 20000
#define E_ 8000
#define F_ 64
#define EPS 1e-10f

#define KSPLIT1 10   // GEMM1: K=N_=20000 -> chunks of 2000 (125 k-tiles of 16)
#define KSPLIT2 4    // GEMM2: K=E_=8000  -> chunks of 2000 (125 k-tiles of 16)

// Scratch (allocation-free rule: __device__ globals)
__device__ float g_dv[N_];
__device__ float g_de[E_];
__device__ float g_Xs[N_ * F_];
__device__ float g_Y[E_ * F_];

// ---------------------------------------------------------------------------
// Zero scratch that gets accumulated via atomics (g_de, g_Y) and the output.
// d_out is poisoned 0xAA by the harness and we atomically accumulate into it.
// ---------------------------------------------------------------------------
__global__ void zero_scratch(float* __restrict__ Z) {
    int i = blockIdx.x * blockDim.x + threadIdx.x;
    if (i < N_ * F_) Z[i] = 0.0f;
    if (i < E_) g_de[i] = 0.0f;
    if (i < E_ * F_) g_Y[i] = 0.0f;
}

// ---------------------------------------------------------------------------
// Fused degree pass: one read of H (640MB) produces d_v (row sums, exact
// ownership -> direct store) and d_e (col sums, per-thread register partials
// -> one atomicAdd per (block, col)).
// Grid: 250 blocks x 256 threads, 80 rows per block.
// ---------------------------------------------------------------------------
__global__ void __launch_bounds__(256) degrees_kernel(const float* __restrict__ H) {
    const int t = threadIdx.x;
    const int r0 = blockIdx.x * 80;
    const int r1 = (r0 + 80 < N_) ? r0 + 80 : N_;

    float de_acc[32];
#pragma unroll
    for (int j = 0; j < 32; j++) de_acc[j] = 0.0f;

    __shared__ float wsum[8];

    for (int r = r0; r < r1; r++) {
        const float* __restrict__ row = H + (size_t)r * E_;
        float rs = 0.0f;
#pragma unroll
        for (int j = 0; j < 32; j++) {
            int c = t + 256 * j;
            if (c < E_) {
                float v = row[c];
                rs += v;
                de_acc[j] += v;
            }
        }
        // block reduction of rs
#pragma unroll
        for (int off = 16; off > 0; off >>= 1)
            rs += __shfl_down_sync(0xffffffffu, rs, off);
        if ((t & 31) == 0) wsum[t >> 5] = rs;
        __syncthreads();
        if (t == 0) {
            float s = 0.0f;
#pragma unroll
            for (int w = 0; w < 8; w++) s += wsum[w];
            g_dv[r] = s;
        }
        __syncthreads();
    }

#pragma unroll
    for (int j = 0; j < 32; j++) {
        int c = t + 256 * j;
        if (c < E_) atomicAdd(&g_de[c], de_acc[j]);
    }
}

// ---------------------------------------------------------------------------
// Xs[n,f] = X[n,f] * rsqrt(d_v[n] + EPS)
// ---------------------------------------------------------------------------
__global__ void scale_x(const float* __restrict__ X) {
    int i = blockIdx.x * blockDim.x + threadIdx.x;
    if (i < N_ * F_) {
        int n = i >> 6;
        g_Xs[i] = X[i] * rsqrtf(g_dv[n] + EPS);
    }
}

// ---------------------------------------------------------------------------
// GEMM1: Y[E,F] += H^T @ Xs  (split-K over N, atomic accumulate)
// Block tile: 256 e x 64 f, K-tile 16. 256 threads, each 8x8 outputs.
// Grid: (ceil(E/256)=32, KSPLIT1=10)
// ---------------------------------------------------------------------------
__global__ void __launch_bounds__(256) gemm1_kernel(const float* __restrict__ H) {
    __shared__ float Hs[16][256];
    __shared__ float Xsm[16][64];

    const int t = threadIdx.x;
    const int tx = t & 7;          // f group: 8 cols
    const int ty = t >> 3;         // e group: 32 rows of 8
    const int e0 = blockIdx.x * 256;
    const int n_begin = blockIdx.y * (N_ / KSPLIT1);  // 2000 per chunk

    float acc[8][8];
#pragma unroll
    for (int i = 0; i < 8; i++)
#pragma unroll
        for (int j = 0; j < 8; j++) acc[i][j] = 0.0f;

    const int e = e0 + t;
    const bool e_ok = (e < E_);

    for (int kt = 0; kt < (N_ / KSPLIT1) / 16; kt++) {
        const int n0 = n_begin + kt * 16;
        // load H tile: Hs[k][e_local]
#pragma unroll
        for (int p = 0; p < 16; p++)
            Hs[p][t] = e_ok ? H[(size_t)(n0 + p) * E_ + e] : 0.0f;
        // load Xs tile: Xsm[k][f]
#pragma unroll
        for (int p = 0; p < 4; p++) {
            int l = p * 256 + t;
            Xsm[l >> 6][l & 63] = g_Xs[(n0 + (l >> 6)) * 64 + (l & 63)];
        }
        __syncthreads();
#pragma unroll
        for (int k = 0; k < 16; k++) {
            float4 a0 = *(const float4*)&Hs[k][ty * 8];
            float4 a1 = *(const float4*)&Hs[k][ty * 8 + 4];
            float4 b0 = *(const float4*)&Xsm[k][tx * 8];
            float4 b1 = *(const float4*)&Xsm[k][tx * 8 + 4];
            float a[8] = {a0.x, a0.y, a0.z, a0.w, a1.x, a1.y, a1.z, a1.w};
            float b[8] = {b0.x, b0.y, b0.z, b0.w, b1.x, b1.y, b1.z, b1.w};
#pragma unroll
            for (int i = 0; i < 8; i++)
#pragma unroll
                for (int j = 0; j < 8; j++) acc[i][j] += a[i] * b[j];
        }
        __syncthreads();
    }

#pragma unroll
    for (int i = 0; i < 8; i++) {
        int eo = e0 + ty * 8 + i;
        if (eo < E_) {
#pragma unroll
            for (int j = 0; j < 8; j++)
                atomicAdd(&g_Y[eo * 64 + tx * 8 + j], acc[i][j]);
        }
    }
}

// ---------------------------------------------------------------------------
// Y[e,f] *= 1/(d_e[e] + EPS)
// ---------------------------------------------------------------------------
__global__ void scale_y() {
    int i = blockIdx.x * blockDim.x + threadIdx.x;
    if (i < E_ * F_) {
        int e = i >> 6;
        g_Y[i] = g_Y[i] * (1.0f / (g_de[e] + EPS));
    }
}

// ---------------------------------------------------------------------------
// GEMM2: Z[N,F] += H @ Y  (split-K over E, atomic accumulate into d_out)
// Block tile: 256 n x 64 f, K-tile 16. Grid: (ceil(N/256)=79, KSPLIT2=4)
// H tile transposed into smem (padded 260 to keep float4 reads aligned and
// conflicts mild).
// ---------------------------------------------------------------------------
__global__ void __launch_bounds__(256) gemm2_kernel(const float* __restrict__ H,
                                                    float* __restrict__ Z) {
    __shared__ float Hs[16][260];
    __shared__ float Ysm[16][64];

    const int t = threadIdx.x;
    const int tx = t & 7;
    const int ty = t >> 3;
    const int n0 = blockIdx.x * 256;
    const int e_begin = blockIdx.y * (E_ / KSPLIT2);  // 2000 per chunk

    float acc[8][8];
#pragma unroll
    for (int i = 0; i < 8; i++)
#pragma unroll
        for (int j = 0; j < 8; j++) acc[i][j] = 0.0f;

    const int col = t & 15;
    const int rsub = t >> 4;

    for (int kt = 0; kt < (E_ / KSPLIT2) / 16; kt++) {
        const int k0 = e_begin + kt * 16;
        // load H tile transposed: Hs[k_local][n_local]
#pragma unroll
        for (int p = 0; p < 16; p++) {
            int row = p * 16 + rsub;
            int n = n0 + row;
            Hs[col][row] = (n < N_) ? H[(size_t)n * E_ + k0 + col] : 0.0f;
        }
        // load Y tile: Ysm[k_local][f]
#pragma unroll
        for (int p = 0; p < 4; p++) {
            int l = p * 256 + t;
            Ysm[l >> 6][l & 63] = g_Y[(k0 + (l >> 6)) * 64 + (l & 63)];
        }
        __syncthreads();
#pragma unroll
        for (int k = 0; k < 16; k++) {
            float4 a0 = *(const float4*)&Hs[k][ty * 8];
            float4 a1 = *(const float4*)&Hs[k][ty * 8 + 4];
            float4 b0 = *(const float4*)&Ysm[k][tx * 8];
            float4 b1 = *(const float4*)&Ysm[k][tx * 8 + 4];
            float a[8] = {a0.x, a0.y, a0.z, a0.w, a1.x, a1.y, a1.z, a1.w};
            float b[8] = {b0.x, b0.y, b0.z, b0.w, b1.x, b1.y, b1.z, b1.w};
#pragma unroll
            for (int i = 0; i < 8; i++)
#pragma unroll
                for (int j = 0; j < 8; j++) acc[i][j] += a[i] * b[j];
        }
        __syncthreads();
    }

#pragma unroll
    for (int i = 0; i < 8; i++) {
        int n = n0 + ty * 8 + i;
        if (n < N_) {
#pragma unroll
            for (int j = 0; j < 8; j++)
                atomicAdd(&Z[n * 64 + tx * 8 + j], acc[i][j]);
        }
    }
}

// ---------------------------------------------------------------------------
// Final: Z[n,f] *= rsqrt(d_v[n] + EPS)
// ---------------------------------------------------------------------------
__global__ void final_scale(float* __restrict__ Z) {
    int i = blockIdx.x * blockDim.x + threadIdx.x;
    if (i < N_ * F_) {
        int n = i >> 6;
        Z[i] = Z[i] * rsqrtf(g_dv[n] + EPS);
    }
}

// ---------------------------------------------------------------------------
extern "C" void kernel_launch(void* const* d_in, const int* in_sizes, int n_in,
                              void* d_out, int out_size) {
    const float* H = (const float*)d_in[0];  // [N_, E_] fp32
    const float* X = (const float*)d_in[1];  // [N_, F_] fp32
    float* Z = (float*)d_out;                // [N_, F_] fp32

    const int nf_blocks = (N_ * F_ + 255) / 256;
    const int ef_blocks = (E_ * F_ + 255) / 256;

    zero_scratch<<<nf_blocks, 256>>>(Z);
    degrees_kernel<<<250, 256>>>(H);
    scale_x<<<nf_blocks, 256>>>(X);
    gemm1_kernel<<<dim3((E_ + 255) / 256, KSPLIT1), 256>>>(H);
    scale_y<<<ef_blocks, 256>>>();
    gemm2_kernel<<<dim3((N_ + 255) / 256, KSPLIT2), 256>>>(H, Z);
    final_scale<<<nf_blocks, 256>>>(Z);
}

// round 4
// speedup vs baseline: 1.6752x; 1.6752x over previous
#include <cuda_runtime.h>
#include <cuda_bf16.h>
#include <cstdint>

#define N_ 20000
#define E_ 8000
#define F_ 64
#define EPS 1e-10f

#define NPAD 20032          // N_ padded to multiple of 64
#define TKC 64              // K elements per chunk
#define TM 128              // M tile
#define NCH1 313            // ceil(N_/64)
#define SPLIT1 7
#define CPS1 45             // ceil(313/7)
#define NCH2 125            // E_/64 exact

// ---------------- scratch ----------------
__device__ float g_dv[N_];
__device__ float g_de[E_];
__device__ float g_Y[E_ * F_];
__device__ unsigned short g_XsTh[64 * NPAD];
__device__ unsigned short g_XsTl[64 * NPAD];
__device__ unsigned short g_YdTh[64 * E_];
__device__ unsigned short g_YdTl[64 * E_];

// ---------------- helpers ----------------
__device__ __forceinline__ uint32_t smem_u32(const void* p) {
    uint32_t a;
    asm("{ .reg .u64 tmp; cvta.to.shared.u64 tmp, %1; cvt.u32.u64 %0, tmp; }"
        : "=r"(a) : "l"(p));
    return a;
}
#define SW128(o) ((uint32_t)(o) ^ (((uint32_t)(o) >> 3) & 0x70))

__device__ __forceinline__ uint32_t pack2(__nv_bfloat16 a, __nv_bfloat16 b) {
    return (uint32_t)__bfloat16_as_ushort(a) |
           ((uint32_t)__bfloat16_as_ushort(b) << 16);
}
__device__ __forceinline__ void split_bf16(float v, __nv_bfloat16& h, __nv_bfloat16& l) {
    h = __float2bfloat16(v);
    l = __float2bfloat16(v - __bfloat162float(h));
}

#define LDMX4(r, addr) \
    asm volatile("ldmatrix.sync.aligned.m8n8.x4.shared.b16 {%0,%1,%2,%3}, [%4];" \
        : "=r"((r)[0]), "=r"((r)[1]), "=r"((r)[2]), "=r"((r)[3]) : "r"(addr))

__device__ __forceinline__ void mma_bf16(float* c, const uint32_t* a,
                                         uint32_t b0, uint32_t b1) {
    asm volatile(
        "mma.sync.aligned.m16n8k16.row.col.f32.bf16.bf16.f32 "
        "{%0,%1,%2,%3}, {%4,%5,%6,%7}, {%8,%9}, {%0,%1,%2,%3};"
        : "+f"(c[0]), "+f"(c[1]), "+f"(c[2]), "+f"(c[3])
        : "r"(a[0]), "r"(a[1]), "r"(a[2]), "r"(a[3]), "r"(b0), "r"(b1));
}

// ---------------- zero scratch ----------------
__global__ void zero_scratch() {
    int i = blockIdx.x * blockDim.x + threadIdx.x;
    if (i < E_ * F_) g_Y[i] = 0.0f;
    if (i < E_) g_de[i] = 0.0f;
}

// ---------------- degrees (one pass over H) ----------------
__global__ void __launch_bounds__(256) degrees_kernel(const float* __restrict__ H) {
    const int t = threadIdx.x;
    const int r0 = blockIdx.x * 80;
    const int r1 = (r0 + 80 < N_) ? r0 + 80 : N_;

    float de_acc[32];
#pragma unroll
    for (int j = 0; j < 32; j++) de_acc[j] = 0.0f;

    __shared__ float wsum[8];

    for (int r = r0; r < r1; r++) {
        const float* __restrict__ row = H + (size_t)r * E_;
        float rs = 0.0f;
#pragma unroll
        for (int j = 0; j < 32; j++) {
            int c = t + 256 * j;
            if (c < E_) {
                float v = row[c];
                rs += v;
                de_acc[j] += v;
            }
        }
#pragma unroll
        for (int off = 16; off > 0; off >>= 1)
            rs += __shfl_down_sync(0xffffffffu, rs, off);
        if ((t & 31) == 0) wsum[t >> 5] = rs;
        __syncthreads();
        if (t == 0) {
            float s = 0.0f;
#pragma unroll
            for (int w = 0; w < 8; w++) s += wsum[w];
            g_dv[r] = s;
        }
        __syncthreads();
    }
#pragma unroll
    for (int j = 0; j < 32; j++) {
        int c = t + 256 * j;
        if (c < E_) atomicAdd(&g_de[c], de_acc[j]);
    }
}

// ---------------- Xs^T materialization (scaled, split bf16, transposed) ------
__global__ void __launch_bounds__(256) scale_x_t(const float* __restrict__ X) {
    __shared__ unsigned short sh[64 * 130];
    __shared__ unsigned short sl[64 * 130];
    const int t = threadIdx.x;
    const int n0 = blockIdx.x * 128;
#pragma unroll
    for (int i = 0; i < 32; i++) {
        int idx = i * 256 + t;
        int nl = idx >> 6, f = idx & 63;
        int n = n0 + nl;
        float v = 0.0f;
        if (n < N_) v = X[(size_t)n * 64 + f] * rsqrtf(g_dv[n] + EPS);
        __nv_bfloat16 h, l;
        split_bf16(v, h, l);
        sh[f * 130 + nl] = __bfloat16_as_ushort(h);
        sl[f * 130 + nl] = __bfloat16_as_ushort(l);
    }
    __syncthreads();
#pragma unroll
    for (int i = 0; i < 32; i++) {
        int idx = i * 256 + t;
        int f = idx >> 7, nl = idx & 127;
        int n = n0 + nl;
        if (n < NPAD) {
            g_XsTh[(size_t)f * NPAD + n] = sh[f * 130 + nl];
            g_XsTl[(size_t)f * NPAD + n] = sl[f * 130 + nl];
        }
    }
}

// ---------------- Yd^T materialization ----------------
__global__ void __launch_bounds__(256) scale_y_t() {
    __shared__ unsigned short sh[64 * 130];
    __shared__ unsigned short sl[64 * 130];
    const int t = threadIdx.x;
    const int e0 = blockIdx.x * 128;
#pragma unroll
    for (int i = 0; i < 32; i++) {
        int idx = i * 256 + t;
        int el = idx >> 6, f = idx & 63;
        int e = e0 + el;
        float v = 0.0f;
        if (e < E_) v = g_Y[(size_t)e * 64 + f] * (1.0f / (g_de[e] + EPS));
        __nv_bfloat16 h, l;
        split_bf16(v, h, l);
        sh[f * 130 + el] = __bfloat16_as_ushort(h);
        sl[f * 130 + el] = __bfloat16_as_ushort(l);
    }
    __syncthreads();
#pragma unroll
    for (int i = 0; i < 32; i++) {
        int idx = i * 256 + t;
        int f = idx >> 7, el = idx & 127;
        int e = e0 + el;
        if (e < E_) {
            g_YdTh[(size_t)f * E_ + e] = sh[f * 130 + el];
            g_YdTl[(size_t)f * E_ + e] = sl[f * 130 + el];
        }
    }
}

// ============================================================================
// Shared MMA core: given A (128 rows x 64 k, split bf16, SW128, pitch 128B)
// and B (64 f-rows x 64 k, split bf16, SW128, pitch 128B), each of 8 warps
// computes a 16(row) x 64(f) fp32 tile: acc[8 f-tiles][4].
// ============================================================================
__device__ __forceinline__ void mma_chunk(uint32_t sbAH, uint32_t sbAL,
                                          uint32_t sbBH, uint32_t sbBL,
                                          int w, int lane, float acc[8][4]) {
    const int wm = w * 16;
    const int g = lane & 7;
    const int mh = (lane >> 3) & 1;
    const int kh = lane >> 4;
    const int fr = (lane >> 4) * 8 + g;      // B: f row within a 16-f group
    const int kb8 = ((lane >> 3) & 1) * 8;   // B: k half
#pragma unroll
    for (int ks = 0; ks < 4; ks++) {
        const int k0l = ks * 16;
        uint32_t ah[4], al[4];
        uint32_t offA = SW128((uint32_t)((wm + mh * 8 + g) * 128 + (k0l + kh * 8) * 2));
        LDMX4(ah, sbAH + offA);
        LDMX4(al, sbAL + offA);
        uint32_t bh[16], bl[16];
#pragma unroll
        for (int fq = 0; fq < 4; fq++) {
            uint32_t offB = SW128((uint32_t)((fq * 16 + fr) * 128 + (k0l + kb8) * 2));
            LDMX4(&bh[fq * 4], sbBH + offB);
            LDMX4(&bl[fq * 4], sbBL + offB);
        }
#pragma unroll
        for (int ft = 0; ft < 8; ft++) {
            uint32_t b0h = bh[(ft >> 1) * 4 + (ft & 1) * 2];
            uint32_t b1h = bh[(ft >> 1) * 4 + (ft & 1) * 2 + 1];
            uint32_t b0l = bl[(ft >> 1) * 4 + (ft & 1) * 2];
            uint32_t b1l = bl[(ft >> 1) * 4 + (ft & 1) * 2 + 1];
            mma_bf16(acc[ft], ah, b0h, b1h);
            mma_bf16(acc[ft], al, b0h, b1h);
            mma_bf16(acc[ft], ah, b0l, b1l);
        }
    }
}

// ---------------- GEMM1: Y[E,64] += H^T · Xs (split-K, atomic epilogue) -----
#define G1_AH 0
#define G1_AL 16384
#define G1_BH 32768
#define G1_BL 40960
#define G1_STAGE 49152
#define STAGE_PITCH 132
#define G1_TOTAL (49152 + 64 * STAGE_PITCH * 4)   // 82944

__global__ void __launch_bounds__(256, 2)
gemm1_kernel(const float* __restrict__ H) {
    extern __shared__ char smem[];
    const uint32_t sb = smem_u32(smem);
    const int t = threadIdx.x;
    const int lane = t & 31, w = t >> 5;
    const int e0 = blockIdx.x * TM;
    const int c_begin = blockIdx.y * CPS1;
    int c_end = c_begin + CPS1;
    if (c_end > NCH1) c_end = NCH1;

    float* stage = (float*)(smem + G1_STAGE);
    float acc[8][4];
#pragma unroll
    for (int i = 0; i < 8; i++)
#pragma unroll
        for (int j = 0; j < 4; j++) acc[i][j] = 0.0f;

    for (int c = c_begin; c < c_end; c++) {
        const int n0 = c * TKC;
        // phase 1: stage H [64 n][128 e] fp32 + B tiles
#pragma unroll
        for (int it = 0; it < 8; it++) {
            int nl = it * 8 + w;
            int n = n0 + nl;
            int e = e0 + lane * 4;
            float4 v = make_float4(0.f, 0.f, 0.f, 0.f);
            if (n < N_ && e < E_) v = *(const float4*)(H + (size_t)n * E_ + e);
            *(float4*)(stage + nl * STAGE_PITCH + lane * 4) = v;
        }
#pragma unroll
        for (int it = 0; it < 2; it++) {
            int f = w * 8 + it * 4 + (lane >> 3);
            int l8 = lane & 7;
            size_t gidx = (size_t)f * NPAD + n0 + l8 * 8;
            uint4 vh = *(const uint4*)(g_XsTh + gidx);
            uint4 vl = *(const uint4*)(g_XsTl + gidx);
            uint32_t bo = (uint32_t)(f * 128 + l8 * 16);
            *(uint4*)(smem + G1_BH + SW128(bo)) = vh;
            *(uint4*)(smem + G1_BL + SW128(bo)) = vl;
        }
        __syncthreads();
        // phase 2: transpose + split-convert stage -> A[e][n]
        {
            int el = t >> 1, half = t & 1;
            const float* colp = stage + (half * 32) * STAGE_PITCH + el;
            uint32_t base = (uint32_t)(el * 128 + half * 64);
#pragma unroll
            for (int j = 0; j < 32; j += 2) {
                float v0 = colp[j * STAGE_PITCH];
                float v1 = colp[(j + 1) * STAGE_PITCH];
                __nv_bfloat16 h0, l0, h1, l1;
                split_bf16(v0, h0, l0);
                split_bf16(v1, h1, l1);
                uint32_t off = base + j * 2;
                *(uint32_t*)(smem + G1_AH + SW128(off)) = pack2(h0, h1);
                *(uint32_t*)(smem + G1_AL + SW128(off)) = pack2(l0, l1);
            }
        }
        __syncthreads();
        // phase 3: MMA
        mma_chunk(sb + G1_AH, sb + G1_AL, sb + G1_BH, sb + G1_BL, w, lane, acc);
        __syncthreads();
    }

    // epilogue: atomic accumulate partials into g_Y
    const int g2 = lane >> 2, tq = lane & 3;
    const int e_lo = e0 + w * 16 + g2;
    const int e_hi = e_lo + 8;
#pragma unroll
    for (int ft = 0; ft < 8; ft++) {
        int f = ft * 8 + tq * 2;
        if (e_lo < E_) {
            atomicAdd(&g_Y[(size_t)e_lo * 64 + f], acc[ft][0]);
            atomicAdd(&g_Y[(size_t)e_lo * 64 + f + 1], acc[ft][1]);
        }
        if (e_hi < E_) {
            atomicAdd(&g_Y[(size_t)e_hi * 64 + f], acc[ft][2]);
            atomicAdd(&g_Y[(size_t)e_hi * 64 + f + 1], acc[ft][3]);
        }
    }
}

// ---------------- GEMM2: Z[N,64] = D_v^{-1/2} · H · Yd ----------------------
#define G2_AH 0
#define G2_AL 16384
#define G2_BH 32768
#define G2_BL 40960
#define G2_TOTAL 49152

__global__ void __launch_bounds__(256, 2)
gemm2_kernel(const float* __restrict__ H, float* __restrict__ Z) {
    extern __shared__ char smem[];
    const uint32_t sb = smem_u32(smem);
    const int t = threadIdx.x;
    const int lane = t & 31, w = t >> 5;
    const int n0 = blockIdx.x * TM;

    float acc[8][4];
#pragma unroll
    for (int i = 0; i < 8; i++)
#pragma unroll
        for (int j = 0; j < 4; j++) acc[i][j] = 0.0f;

    for (int c = 0; c < NCH2; c++) {
        const int k0 = c * TKC;
        // phase 1: A = H rows (K-contiguous), load+convert+store split bf16
#pragma unroll
        for (int it = 0; it < 8; it++) {
            int r = it * 16 + w * 2 + (lane >> 4);
            int l16 = lane & 15;
            int n = n0 + r;
            float4 v = make_float4(0.f, 0.f, 0.f, 0.f);
            if (n < N_) v = *(const float4*)(H + (size_t)n * E_ + k0 + l16 * 4);
            __nv_bfloat16 h0, l0, h1, l1, h2, l2, h3, l3;
            split_bf16(v.x, h0, l0);
            split_bf16(v.y, h1, l1);
            split_bf16(v.z, h2, l2);
            split_bf16(v.w, h3, l3);
            uint32_t off = (uint32_t)(r * 128 + l16 * 8);
            uint2 ph_ = make_uint2(pack2(h0, h1), pack2(h2, h3));
            uint2 pl_ = make_uint2(pack2(l0, l1), pack2(l2, l3));
            *(uint2*)(smem + G2_AH + SW128(off)) = ph_;
            *(uint2*)(smem + G2_AL + SW128(off)) = pl_;
        }
        // B tiles from YdT (K-contiguous, already split bf16)
#pragma unroll
        for (int it = 0; it < 2; it++) {
            int f = w * 8 + it * 4 + (lane >> 3);
            int l8 = lane & 7;
            size_t gidx = (size_t)f * E_ + k0 + l8 * 8;
            uint4 vh = *(const uint4*)(g_YdTh + gidx);
            uint4 vl = *(const uint4*)(g_YdTl + gidx);
            uint32_t bo = (uint32_t)(f * 128 + l8 * 16);
            *(uint4*)(smem + G2_BH + SW128(bo)) = vh;
            *(uint4*)(smem + G2_BL + SW128(bo)) = vl;
        }
        __syncthreads();
        // phase 2: MMA
        mma_chunk(sb + G2_AH, sb + G2_AL, sb + G2_BH, sb + G2_BL, w, lane, acc);
        __syncthreads();
    }

    // epilogue: scale by rsqrt(d_v) and store directly
    const int g2 = lane >> 2, tq = lane & 3;
    const int n_lo = n0 + w * 16 + g2;
    const int n_hi = n_lo + 8;
    float s_lo = (n_lo < N_) ? rsqrtf(g_dv[n_lo] + EPS) : 0.0f;
    float s_hi = (n_hi < N_) ? rsqrtf(g_dv[n_hi] + EPS) : 0.0f;
#pragma unroll
    for (int ft = 0; ft < 8; ft++) {
        int f = ft * 8 + tq * 2;
        if (n_lo < N_) {
            float2 o = make_float2(acc[ft][0] * s_lo, acc[ft][1] * s_lo);
            *(float2*)(Z + (size_t)n_lo * 64 + f) = o;
        }
        if (n_hi < N_) {
            float2 o = make_float2(acc[ft][2] * s_hi, acc[ft][3] * s_hi);
            *(float2*)(Z + (size_t)n_hi * 64 + f) = o;
        }
    }
}

// ---------------------------------------------------------------------------
extern "C" void kernel_launch(void* const* d_in, const int* in_sizes, int n_in,
                              void* d_out, int out_size) {
    const float* H = (const float*)d_in[0];  // [N_, E_] fp32
    const float* X = (const float*)d_in[1];  // [N_, F_] fp32
    float* Z = (float*)d_out;                // [N_, F_] fp32

    cudaFuncSetAttribute(gemm1_kernel, cudaFuncAttributeMaxDynamicSharedMemorySize, G1_TOTAL);
    cudaFuncSetAttribute(gemm2_kernel, cudaFuncAttributeMaxDynamicSharedMemorySize, G2_TOTAL);

    zero_scratch<<<(E_ * F_ + 255) / 256, 256>>>();
    degrees_kernel<<<250, 256>>>(H);
    scale_x_t<<<(NPAD + 127) / 128, 256>>>(X);
    gemm1_kernel<<<dim3((E_ + TM - 1) / TM, SPLIT1), 256, G1_TOTAL>>>(H);
    scale_y_t<<<(E_ + 127) / 128, 256>>>();
    gemm2_kernel<<<(N_ + TM - 1) / TM, 256, G2_TOTAL>>>(H, Z);
}

// round 5
// speedup vs baseline: 2.3728x; 1.4164x over previous
#include <cuda_runtime.h>
#include <cuda_bf16.h>
#include <cstdint>

#define N_ 20000
#define E_ 8000
#define F_ 64
#define EPS 1e-10f

#define NPAD 20032          // N_ padded to multiple of 64
#define NCH1 313            // ceil(N_/64)
#define SPLIT1 7
#define CPS1 45             // ceil(313/7)
#define ETILES1 63          // ceil(E_/128)
#define NCH2 125            // E_/64
#define NTILES2 157         // ceil(N_/128)

// ---------------- scratch ----------------
__device__ float g_dv[N_];
__device__ float g_de[E_];
__device__ float g_YT[64 * E_];            // Y^T [f][e]
__device__ unsigned short g_XsTh[64 * NPAD];
__device__ unsigned short g_XsTl[64 * NPAD];
__device__ unsigned short g_YdTh[64 * E_]; // [f][e]
__device__ unsigned short g_YdTl[64 * E_];

// ---------------- helpers ----------------
__device__ __forceinline__ uint32_t smem_u32(const void* p) {
    uint32_t a;
    asm("{ .reg .u64 tmp; cvta.to.shared.u64 tmp, %1; cvt.u32.u64 %0, tmp; }"
        : "=r"(a) : "l"(p));
    return a;
}
#define SW128(o) ((uint32_t)(o) ^ (((uint32_t)(o) >> 3) & 0x70))

__device__ __forceinline__ uint32_t pack2(__nv_bfloat16 a, __nv_bfloat16 b) {
    return (uint32_t)__bfloat16_as_ushort(a) |
           ((uint32_t)__bfloat16_as_ushort(b) << 16);
}
__device__ __forceinline__ void split_bf16(float v, __nv_bfloat16& h, __nv_bfloat16& l) {
    h = __float2bfloat16(v);
    l = __float2bfloat16(v - __bfloat162float(h));
}

#define LDMX4(r, addr) \
    asm volatile("ldmatrix.sync.aligned.m8n8.x4.shared.b16 {%0,%1,%2,%3}, [%4];" \
        : "=r"((r)[0]), "=r"((r)[1]), "=r"((r)[2]), "=r"((r)[3]) : "r"(addr))
#define LDMX4T(r, addr) \
    asm volatile("ldmatrix.sync.aligned.m8n8.x4.trans.shared.b16 {%0,%1,%2,%3}, [%4];" \
        : "=r"((r)[0]), "=r"((r)[1]), "=r"((r)[2]), "=r"((r)[3]) : "r"(addr))

__device__ __forceinline__ void mma_bf16(float* c, const uint32_t* a,
                                         uint32_t b0, uint32_t b1) {
    asm volatile(
        "mma.sync.aligned.m16n8k16.row.col.f32.bf16.bf16.f32 "
        "{%0,%1,%2,%3}, {%4,%5,%6,%7}, {%8,%9}, {%0,%1,%2,%3};"
        : "+f"(c[0]), "+f"(c[1]), "+f"(c[2]), "+f"(c[3])
        : "r"(a[0]), "r"(a[1]), "r"(a[2]), "r"(a[3]), "r"(b0), "r"(b1));
}

__device__ __forceinline__ void cp_async16(uint32_t dst, const void* src, int srcsz) {
    asm volatile("cp.async.cg.shared.global [%0], [%1], 16, %2;"
                 :: "r"(dst), "l"(src), "r"(srcsz) : "memory");
}
#define CP_COMMIT() asm volatile("cp.async.commit_group;" ::: "memory")
#define CP_WAIT1()  asm volatile("cp.async.wait_group 1;" ::: "memory")
#define CP_WAIT0()  asm volatile("cp.async.wait_group 0;" ::: "memory")

// ---------------- zero scratch ----------------
__global__ void zero_scratch() {
    int i = blockIdx.x * blockDim.x + threadIdx.x;
    if (i < 64 * E_) g_YT[i] = 0.0f;
    if (i < E_) g_de[i] = 0.0f;
}

// ---------------- degrees (one pass over H), 444 blocks = 3 waves ----------
__global__ void __launch_bounds__(256) degrees_kernel(const float* __restrict__ H) {
    const int t = threadIdx.x;
    const int r0 = blockIdx.x * 46;
    const int r1 = (r0 + 46 < N_) ? r0 + 46 : N_;

    float de_acc[32];
#pragma unroll
    for (int j = 0; j < 32; j++) de_acc[j] = 0.0f;

    __shared__ float wsum[8];

    for (int r = r0; r < r1; r++) {
        const float* __restrict__ row = H + (size_t)r * E_;
        float rs = 0.0f;
#pragma unroll
        for (int j = 0; j < 32; j++) {
            int c = t + 256 * j;
            if (c < E_) {
                float v = row[c];
                rs += v;
                de_acc[j] += v;
            }
        }
#pragma unroll
        for (int off = 16; off > 0; off >>= 1)
            rs += __shfl_down_sync(0xffffffffu, rs, off);
        if ((t & 31) == 0) wsum[t >> 5] = rs;
        __syncthreads();
        if (t == 0) {
            float s = 0.0f;
#pragma unroll
            for (int w = 0; w < 8; w++) s += wsum[w];
            g_dv[r] = s;
        }
        __syncthreads();
    }
#pragma unroll
    for (int j = 0; j < 32; j++) {
        int c = t + 256 * j;
        if (c < E_) atomicAdd(&g_de[c], de_acc[j]);
    }
}

// ---------------- Xs^T materialization (scaled, split bf16, transposed) ------
__global__ void __launch_bounds__(256) scale_x_t(const float* __restrict__ X) {
    __shared__ unsigned short sh[64 * 130];
    __shared__ unsigned short sl[64 * 130];
    const int t = threadIdx.x;
    const int n0 = blockIdx.x * 128;
#pragma unroll
    for (int i = 0; i < 32; i++) {
        int idx = i * 256 + t;
        int nl = idx >> 6, f = idx & 63;
        int n = n0 + nl;
        float v = 0.0f;
        if (n < N_) v = X[(size_t)n * 64 + f] * rsqrtf(g_dv[n] + EPS);
        __nv_bfloat16 h, l;
        split_bf16(v, h, l);
        sh[f * 130 + nl] = __bfloat16_as_ushort(h);
        sl[f * 130 + nl] = __bfloat16_as_ushort(l);
    }
    __syncthreads();
#pragma unroll
    for (int i = 0; i < 32; i++) {
        int idx = i * 256 + t;
        int f = idx >> 7, nl = idx & 127;
        int n = n0 + nl;
        if (n < NPAD) {
            g_XsTh[(size_t)f * NPAD + n] = sh[f * 130 + nl];
            g_XsTl[(size_t)f * NPAD + n] = sl[f * 130 + nl];
        }
    }
}

// ---------------- Yd^T: pure elementwise scale + split (f-major already) ----
__global__ void __launch_bounds__(256) scale_y_t() {
    int i = blockIdx.x * blockDim.x + threadIdx.x;
    if (i < 64 * E_) {
        int e = i % E_;
        float v = g_YT[i] * (1.0f / (g_de[e] + EPS));
        __nv_bfloat16 h, l;
        split_bf16(v, h, l);
        g_YdTh[i] = __bfloat16_as_ushort(h);
        g_YdTl[i] = __bfloat16_as_ushort(l);
    }
}

// ============================================================================
// GEMM1: Y^T[64 f, E] += Xs^T[64 f, N] · H[N, E]
// A = XsT (row-major, k contiguous), B = H tile [k=n][e] loaded with
// ldmatrix.trans. Block: 128-e tile x full 64 f, split-K over n (SPLIT1).
// smem: XH 8K @0 | XL @8192 | HH 16K @16384 (two 64x64 e-half tiles) |
//       HL @32768 | STAGE fp32 2x32K @49152.  Total 114688 B.
// ============================================================================
#define G1_XH 0
#define G1_XL 8192
#define G1_HH 16384
#define G1_HL 32768
#define G1_STG 49152
#define G_TOTAL 114688

__global__ void __launch_bounds__(256, 2)
gemm1_kernel(const float* __restrict__ H) {
    extern __shared__ char smem[];
    const uint32_t sb = smem_u32(smem);
    const int t = threadIdx.x;
    const int lane = t & 31, w = t >> 5;
    const int e0 = blockIdx.x * 128;
    const int c_begin = blockIdx.y * CPS1;
    int c_end = c_begin + CPS1;
    if (c_end > NCH1) c_end = NCH1;
    const int nch = c_end - c_begin;

    const int wf = w >> 2;          // 0..1 : 32-f slice
    const int we = w & 3;           // 0..3 : 32-e slice
    const int half = we >> 1;       // e-half tile
    const int ebl = (we & 1) * 32;  // e offset within half

    float acc[2][4][4];
#pragma unroll
    for (int a = 0; a < 2; a++)
#pragma unroll
        for (int b = 0; b < 4; b++)
#pragma unroll
            for (int q = 0; q < 4; q++) acc[a][b][q] = 0.0f;

    // prologue: stage chunk 0
    {
        int n0 = c_begin * 64;
        int e = e0 + lane * 4;
#pragma unroll
        for (int i = 0; i < 8; i++) {
            int k = i * 8 + w;
            int n = n0 + k;
            int ok = (n < N_ && e < E_) ? 16 : 0;
            const float* src = ok ? (H + (size_t)n * E_ + e) : H;
            cp_async16(sb + G1_STG + k * 512 + lane * 16, src, ok);
        }
        CP_COMMIT();
    }

    for (int c = 0; c < nch; c++) {
        const int buf = c & 1;
        const int n0 = (c_begin + c) * 64;

        // B (XsT) prefetch into regs
        uint4 pbh[2], pbl[2];
        {
            int f = t >> 2;
#pragma unroll
            for (int j = 0; j < 2; j++) {
                int sg = (t & 3) + j * 4;
                size_t g = (size_t)f * NPAD + n0 + sg * 8;
                pbh[j] = *(const uint4*)(g_XsTh + g);
                pbl[j] = *(const uint4*)(g_XsTl + g);
            }
        }
        // issue stage for c+1
        if (c + 1 < nch) {
            int n1 = (c_begin + c + 1) * 64;
            int e = e0 + lane * 4;
#pragma unroll
            for (int i = 0; i < 8; i++) {
                int k = i * 8 + w;
                int n = n1 + k;
                int ok = (n < N_ && e < E_) ? 16 : 0;
                const float* src = ok ? (H + (size_t)n * E_ + e) : H;
                cp_async16(sb + G1_STG + (buf ^ 1) * 32768 + k * 512 + lane * 16, src, ok);
            }
            CP_COMMIT();
            CP_WAIT1();
        } else {
            CP_WAIT0();
        }
        __syncthreads();   // stage[buf] visible; prev MMA done (bufs reusable)

        // convert stage -> HH/HL (bf16 split, two e-half SW128 tiles)
        {
            const char* stg = smem + G1_STG + buf * 32768;
            int hh = lane >> 4;
            int el = (lane & 15) * 4;
#pragma unroll
            for (int i = 0; i < 8; i++) {
                int k = i * 8 + w;
                float4 v = *(const float4*)(stg + k * 512 + lane * 16);
                __nv_bfloat16 h0, l0, h1, l1, h2, l2, h3, l3;
                split_bf16(v.x, h0, l0);
                split_bf16(v.y, h1, l1);
                split_bf16(v.z, h2, l2);
                split_bf16(v.w, h3, l3);
                uint32_t off = SW128((uint32_t)(k * 128 + el * 2));
                *(uint2*)(smem + G1_HH + hh * 8192 + off) =
                    make_uint2(pack2(h0, h1), pack2(h2, h3));
                *(uint2*)(smem + G1_HL + hh * 8192 + off) =
                    make_uint2(pack2(l0, l1), pack2(l2, l3));
            }
        }
        // store B regs
        {
            int f = t >> 2;
#pragma unroll
            for (int j = 0; j < 2; j++) {
                int sg = (t & 3) + j * 4;
                uint32_t off = SW128((uint32_t)(f * 128 + sg * 16));
                *(uint4*)(smem + G1_XH + off) = pbh[j];
                *(uint4*)(smem + G1_XL + off) = pbl[j];
            }
        }
        __syncthreads();

        // MMA
#pragma unroll
        for (int ks = 0; ks < 4; ks++) {
            uint32_t ah[2][4], al[2][4];
#pragma unroll
            for (int mt = 0; mt < 2; mt++) {
                int rf = wf * 32 + mt * 16 + (lane & 15);
                uint32_t off = SW128((uint32_t)(rf * 128 + (ks * 16 + (lane >> 4) * 8) * 2));
                LDMX4(ah[mt], sb + G1_XH + off);
                LDMX4(al[mt], sb + G1_XL + off);
            }
#pragma unroll
            for (int pr = 0; pr < 2; pr++) {
                uint32_t bh[4], bl[4];
                int gq = lane >> 3, j = lane & 7;
                int rk = ks * 16 + (gq & 1) * 8 + j;
                int ce = ebl + pr * 16 + (gq >> 1) * 8;
                uint32_t off = SW128((uint32_t)(rk * 128 + ce * 2));
                LDMX4T(bh, sb + G1_HH + half * 8192 + off);
                LDMX4T(bl, sb + G1_HL + half * 8192 + off);
#pragma unroll
                for (int mt = 0; mt < 2; mt++)
#pragma unroll
                    for (int sub = 0; sub < 2; sub++) {
                        float* cc = acc[mt][pr * 2 + sub];
                        mma_bf16(cc, ah[mt], bh[sub * 2], bh[sub * 2 + 1]);
                        mma_bf16(cc, al[mt], bh[sub * 2], bh[sub * 2 + 1]);
                        mma_bf16(cc, ah[mt], bl[sub * 2], bl[sub * 2 + 1]);
                    }
            }
        }
    }

    // epilogue: atomic accumulate into g_YT [f][e]
#pragma unroll
    for (int mt = 0; mt < 2; mt++) {
        int f = wf * 32 + mt * 16 + (lane >> 2);
#pragma unroll
        for (int q = 0; q < 4; q++) {
            int e = e0 + we * 32 + q * 8 + (lane & 3) * 2;
            if (e < E_) {
                atomicAdd(&g_YT[(size_t)f * E_ + e], acc[mt][q][0]);
                atomicAdd(&g_YT[(size_t)f * E_ + e + 1], acc[mt][q][1]);
                atomicAdd(&g_YT[(size_t)(f + 8) * E_ + e], acc[mt][q][2]);
                atomicAdd(&g_YT[(size_t)(f + 8) * E_ + e + 1], acc[mt][q][3]);
            }
        }
    }
}

// ============================================================================
// GEMM2: Z[N,64] = D_v^{-1/2} · H[N,E] · Yd  (B = YdT [f][k=e], no split-K)
// smem: YH 8K @0 | YL @8192 | AH [n][k] 16K @16384 | AL @32768 | STAGE @49152.
// ============================================================================
#define G2_YH 0
#define G2_YL 8192
#define G2_AH 16384
#define G2_AL 32768
#define G2_STG 49152

__global__ void __launch_bounds__(256, 2)
gemm2_kernel(const float* __restrict__ H, float* __restrict__ Z) {
    extern __shared__ char smem[];
    const uint32_t sb = smem_u32(smem);
    const int t = threadIdx.x;
    const int lane = t & 31, w = t >> 5;
    const int n0 = blockIdx.x * 128;

    const int wn = w >> 1;   // 0..3 : 32-n slice
    const int wfc = w & 1;   // 0..1 : 32-f slice

    float acc[2][4][4];
#pragma unroll
    for (int a = 0; a < 2; a++)
#pragma unroll
        for (int b = 0; b < 4; b++)
#pragma unroll
            for (int q = 0; q < 4; q++) acc[a][b][q] = 0.0f;

    // prologue: stage chunk 0   ([128 n][64 k] fp32, 256B rows)
    {
#pragma unroll
        for (int i = 0; i < 8; i++) {
            int r = i * 16 + (t >> 4);
            int n = n0 + r;
            int ok = (n < N_) ? 16 : 0;
            const float* src = ok ? (H + (size_t)n * E_ + (t & 15) * 4) : H;
            cp_async16(sb + G2_STG + r * 256 + (t & 15) * 16, src, ok);
        }
        CP_COMMIT();
    }

    for (int c = 0; c < NCH2; c++) {
        const int buf = c & 1;
        const int k0 = c * 64;

        // B (YdT) prefetch into regs
        uint4 pbh[2], pbl[2];
        {
            int f = t >> 2;
#pragma unroll
            for (int j = 0; j < 2; j++) {
                int sg = (t & 3) + j * 4;
                size_t g = (size_t)f * E_ + k0 + sg * 8;
                pbh[j] = *(const uint4*)(g_YdTh + g);
                pbl[j] = *(const uint4*)(g_YdTl + g);
            }
        }
        // issue stage for c+1
        if (c + 1 < NCH2) {
            int k1 = (c + 1) * 64;
#pragma unroll
            for (int i = 0; i < 8; i++) {
                int r = i * 16 + (t >> 4);
                int n = n0 + r;
                int ok = (n < N_) ? 16 : 0;
                const float* src = ok ? (H + (size_t)n * E_ + k1 + (t & 15) * 4) : H;
                cp_async16(sb + G2_STG + (buf ^ 1) * 32768 + r * 256 + (t & 15) * 16, src, ok);
            }
            CP_COMMIT();
            CP_WAIT1();
        } else {
            CP_WAIT0();
        }
        __syncthreads();

        // convert stage -> AH/AL ([n][k] bf16 SW128 128B rows)
        {
            const char* stg = smem + G2_STG + buf * 32768;
#pragma unroll
            for (int i = 0; i < 8; i++) {
                int r = i * 16 + (t >> 4);
                int kl = (t & 15) * 4;
                float4 v = *(const float4*)(stg + r * 256 + (t & 15) * 16);
                __nv_bfloat16 h0, l0, h1, l1, h2, l2, h3, l3;
                split_bf16(v.x, h0, l0);
                split_bf16(v.y, h1, l1);
                split_bf16(v.z, h2, l2);
                split_bf16(v.w, h3, l3);
                uint32_t off = SW128((uint32_t)(r * 128 + kl * 2));
                *(uint2*)(smem + G2_AH + off) = make_uint2(pack2(h0, h1), pack2(h2, h3));
                *(uint2*)(smem + G2_AL + off) = make_uint2(pack2(l0, l1), pack2(l2, l3));
            }
        }
        // store B regs
        {
            int f = t >> 2;
#pragma unroll
            for (int j = 0; j < 2; j++) {
                int sg = (t & 3) + j * 4;
                uint32_t off = SW128((uint32_t)(f * 128 + sg * 16));
                *(uint4*)(smem + G2_YH + off) = pbh[j];
                *(uint4*)(smem + G2_YL + off) = pbl[j];
            }
        }
        __syncthreads();

        // MMA
#pragma unroll
        for (int ks = 0; ks < 4; ks++) {
            uint32_t ah[2][4], al[2][4];
#pragma unroll
            for (int mt = 0; mt < 2; mt++) {
                int rn = wn * 32 + mt * 16 + (lane & 15);
                uint32_t off = SW128((uint32_t)(rn * 128 + (ks * 16 + (lane >> 4) * 8) * 2));
                LDMX4(ah[mt], sb + G2_AH + off);
                LDMX4(al[mt], sb + G2_AL + off);
            }
#pragma unroll
            for (int nt = 0; nt < 2; nt++) {
                uint32_t bh[4], bl[4];
                int fr = wfc * 32 + nt * 16 + (lane >> 4) * 8 + (lane & 7);
                int kb8 = ((lane >> 3) & 1) * 8;
                uint32_t off = SW128((uint32_t)(fr * 128 + (ks * 16 + kb8) * 2));
                LDMX4(bh, sb + G2_YH + off);
                LDMX4(bl, sb + G2_YL + off);
#pragma unroll
                for (int mt = 0; mt < 2; mt++)
#pragma unroll
                    for (int sub = 0; sub < 2; sub++) {
                        float* cc = acc[mt][nt * 2 + sub];
                        mma_bf16(cc, ah[mt], bh[sub * 2], bh[sub * 2 + 1]);
                        mma_bf16(cc, al[mt], bh[sub * 2], bh[sub * 2 + 1]);
                        mma_bf16(cc, ah[mt], bl[sub * 2], bl[sub * 2 + 1]);
                    }
            }
        }
    }

    // epilogue: scale by rsqrt(d_v) and store
#pragma unroll
    for (int mt = 0; mt < 2; mt++) {
        int n_lo = n0 + wn * 32 + mt * 16 + (lane >> 2);
        int n_hi = n_lo + 8;
        float s_lo = (n_lo < N_) ? rsqrtf(g_dv[n_lo] + EPS) : 0.0f;
        float s_hi = (n_hi < N_) ? rsqrtf(g_dv[n_hi] + EPS) : 0.0f;
#pragma unroll
        for (int q = 0; q < 4; q++) {
            int f = wfc * 32 + q * 8 + (lane & 3) * 2;
            if (n_lo < N_)
                *(float2*)(Z + (size_t)n_lo * 64 + f) =
                    make_float2(acc[mt][q][0] * s_lo, acc[mt][q][1] * s_lo);
            if (n_hi < N_)
                *(float2*)(Z + (size_t)n_hi * 64 + f) =
                    make_float2(acc[mt][q][2] * s_hi, acc[mt][q][3] * s_hi);
        }
    }
}

// ---------------------------------------------------------------------------
extern "C" void kernel_launch(void* const* d_in, const int* in_sizes, int n_in,
                              void* d_out, int out_size) {
    const float* H = (const float*)d_in[0];  // [N_, E_] fp32
    const float* X = (const float*)d_in[1];  // [N_, F_] fp32
    float* Z = (float*)d_out;                // [N_, F_] fp32

    cudaFuncSetAttribute(gemm1_kernel, cudaFuncAttributeMaxDynamicSharedMemorySize, G_TOTAL);
    cudaFuncSetAttribute(gemm2_kernel, cudaFuncAttributeMaxDynamicSharedMemorySize, G_TOTAL);

    zero_scratch<<<(64 * E_ + 255) / 256, 256>>>();
    degrees_kernel<<<444, 256>>>(H);
    scale_x_t<<<(NPAD + 127) / 128, 256>>>(X);
    gemm1_kernel<<<dim3(ETILES1, SPLIT1), 256, G_TOTAL>>>(H);
    scale_y_t<<<(64 * E_ + 255) / 256, 256>>>();
    gemm2_kernel<<<NTILES2, 256, G_TOTAL>>>(H, Z);
}

// round 6
// speedup vs baseline: 2.7515x; 1.1596x over previous
#include <cuda_runtime.h>
#include <cuda_bf16.h>
#include <cstdint>

#define N_ 20000
#define E_ 8000
#define F_ 64
#define EPS 1e-10f

#define NPAD 20032          // N_ padded to multiple of 64
#define NCH1 313            // ceil(N_/64)
#define SPLIT1 9
#define CPS1 35             // ceil(313/9)
#define ETILES1 63          // ceil(E_/128)
#define NCH2 125            // E_/8000/64
#define SPLIT2 3
#define CPS2 42             // ceil(125/3)
#define NTILES2 157         // ceil(N_/128)

// per-buffer smem layout (both gemms): P0 8K, P1 8K, Q0 16K, Q1 16K
#define OFF_P0 0
#define OFF_P1 8192
#define OFF_Q0 16384
#define OFF_Q1 32768
#define BUFSTRIDE 49152
#define G_TOTAL (2 * BUFSTRIDE)   // 98304

// ---------------- scratch ----------------
__device__ float g_dv[N_];
__device__ float g_de[E_];
__device__ float g_YT[64 * E_];            // Y^T [f][e]
__device__ unsigned short g_XsTh[64 * NPAD];
__device__ unsigned short g_XsTl[64 * NPAD];
__device__ unsigned short g_YdTh[64 * E_]; // [f][e]
__device__ unsigned short g_YdTl[64 * E_];

// ---------------- helpers ----------------
__device__ __forceinline__ uint32_t smem_u32(const void* p) {
    uint32_t a;
    asm("{ .reg .u64 tmp; cvta.to.shared.u64 tmp, %1; cvt.u32.u64 %0, tmp; }"
        : "=r"(a) : "l"(p));
    return a;
}
#define SW128(o) ((uint32_t)(o) ^ (((uint32_t)(o) >> 3) & 0x70))

__device__ __forceinline__ uint32_t pack2(__nv_bfloat16 a, __nv_bfloat16 b) {
    return (uint32_t)__bfloat16_as_ushort(a) |
           ((uint32_t)__bfloat16_as_ushort(b) << 16);
}
__device__ __forceinline__ void split_bf16(float v, __nv_bfloat16& h, __nv_bfloat16& l) {
    h = __float2bfloat16(v);
    l = __float2bfloat16(v - __bfloat162float(h));
}
__device__ __forceinline__ void cvt_pair(float4 v, uint2& hi, uint2& lo) {
    __nv_bfloat16 h0, l0, h1, l1, h2, l2, h3, l3;
    split_bf16(v.x, h0, l0);
    split_bf16(v.y, h1, l1);
    split_bf16(v.z, h2, l2);
    split_bf16(v.w, h3, l3);
    hi = make_uint2(pack2(h0, h1), pack2(h2, h3));
    lo = make_uint2(pack2(l0, l1), pack2(l2, l3));
}

#define LDMX4(r, addr) \
    asm volatile("ldmatrix.sync.aligned.m8n8.x4.shared.b16 {%0,%1,%2,%3}, [%4];" \
        : "=r"((r)[0]), "=r"((r)[1]), "=r"((r)[2]), "=r"((r)[3]) : "r"(addr))
#define LDMX4T(r, addr) \
    asm volatile("ldmatrix.sync.aligned.m8n8.x4.trans.shared.b16 {%0,%1,%2,%3}, [%4];" \
        : "=r"((r)[0]), "=r"((r)[1]), "=r"((r)[2]), "=r"((r)[3]) : "r"(addr))

__device__ __forceinline__ void mma_bf16(float* c, const uint32_t* a,
                                         uint32_t b0, uint32_t b1) {
    asm volatile(
        "mma.sync.aligned.m16n8k16.row.col.f32.bf16.bf16.f32 "
        "{%0,%1,%2,%3}, {%4,%5,%6,%7}, {%8,%9}, {%0,%1,%2,%3};"
        : "+f"(c[0]), "+f"(c[1]), "+f"(c[2]), "+f"(c[3])
        : "r"(a[0]), "r"(a[1]), "r"(a[2]), "r"(a[3]), "r"(b0), "r"(b1));
}

// ---------------- zero scratch (incl. output) ----------------
__global__ void zero_scratch(float* __restrict__ Z) {
    int i = blockIdx.x * blockDim.x + threadIdx.x;
    if (i < N_ * F_) Z[i] = 0.0f;
    if (i < 64 * E_) g_YT[i] = 0.0f;
    if (i < E_) g_de[i] = 0.0f;
}

// ---------------- degrees (one pass over H) ----------------
__global__ void __launch_bounds__(256) degrees_kernel(const float* __restrict__ H) {
    const int t = threadIdx.x;
    const int r0 = blockIdx.x * 46;
    const int r1 = (r0 + 46 < N_) ? r0 + 46 : N_;

    float de_acc[32];
#pragma unroll
    for (int j = 0; j < 32; j++) de_acc[j] = 0.0f;

    __shared__ float wsum[8];

    for (int r = r0; r < r1; r++) {
        const float* __restrict__ row = H + (size_t)r * E_;
        float rs = 0.0f;
#pragma unroll
        for (int j = 0; j < 32; j++) {
            int c = t + 256 * j;
            if (c < E_) {
                float v = row[c];
                rs += v;
                de_acc[j] += v;
            }
        }
#pragma unroll
        for (int off = 16; off > 0; off >>= 1)
            rs += __shfl_down_sync(0xffffffffu, rs, off);
        if ((t & 31) == 0) wsum[t >> 5] = rs;
        __syncthreads();
        if (t == 0) {
            float s = 0.0f;
#pragma unroll
            for (int w = 0; w < 8; w++) s += wsum[w];
            g_dv[r] = s;
        }
        __syncthreads();
    }
#pragma unroll
    for (int j = 0; j < 32; j++) {
        int c = t + 256 * j;
        if (c < E_) atomicAdd(&g_de[c], de_acc[j]);
    }
}

// ---------------- Xs^T materialization (scaled, split bf16, transposed) ------
__global__ void __launch_bounds__(256) scale_x_t(const float* __restrict__ X) {
    __shared__ unsigned short sh[64 * 130];
    __shared__ unsigned short sl[64 * 130];
    const int t = threadIdx.x;
    const int n0 = blockIdx.x * 128;
#pragma unroll
    for (int i = 0; i < 32; i++) {
        int idx = i * 256 + t;
        int nl = idx >> 6, f = idx & 63;
        int n = n0 + nl;
        float v = 0.0f;
        if (n < N_) v = X[(size_t)n * 64 + f] * rsqrtf(g_dv[n] + EPS);
        __nv_bfloat16 h, l;
        split_bf16(v, h, l);
        sh[f * 130 + nl] = __bfloat16_as_ushort(h);
        sl[f * 130 + nl] = __bfloat16_as_ushort(l);
    }
    __syncthreads();
#pragma unroll
    for (int i = 0; i < 32; i++) {
        int idx = i * 256 + t;
        int f = idx >> 7, nl = idx & 127;
        int n = n0 + nl;
        if (n < NPAD) {
            g_XsTh[(size_t)f * NPAD + n] = sh[f * 130 + nl];
            g_XsTl[(size_t)f * NPAD + n] = sl[f * 130 + nl];
        }
    }
}

// ---------------- Yd^T: elementwise scale + split (f-major) ----------------
__global__ void __launch_bounds__(256) scale_y_t() {
    int i = blockIdx.x * blockDim.x + threadIdx.x;
    if (i < 64 * E_) {
        int e = i % E_;
        float v = g_YT[i] * (1.0f / (g_de[e] + EPS));
        __nv_bfloat16 h, l;
        split_bf16(v, h, l);
        g_YdTh[i] = __bfloat16_as_ushort(h);
        g_YdTl[i] = __bfloat16_as_ushort(l);
    }
}

// ============================================================================
// GEMM1: Y^T[64 f, E] += Xs^T[64 f, N] · H[N, E]
// per-buf: P0/P1 = XsT hi/lo [64f][64k], Q0/Q1 = H hi/lo (two 64x64 e-halves).
// ============================================================================
__device__ __forceinline__ void g1_ks(uint32_t sbo, int ks, int wf, int half,
                                      int ebl, int lane, float acc[2][4][4]) {
    uint32_t ah[2][4], al[2][4];
#pragma unroll
    for (int mt = 0; mt < 2; mt++) {
        int rf = wf * 32 + mt * 16 + (lane & 15);
        uint32_t off = SW128((uint32_t)(rf * 128 + (ks * 16 + (lane >> 4) * 8) * 2));
        LDMX4(ah[mt], sbo + OFF_P0 + off);
        LDMX4(al[mt], sbo + OFF_P1 + off);
    }
#pragma unroll
    for (int pr = 0; pr < 2; pr++) {
        uint32_t bh[4], bl[4];
        int gq = lane >> 3, j = lane & 7;
        int rk = ks * 16 + (gq & 1) * 8 + j;
        int ce = ebl + pr * 16 + (gq >> 1) * 8;
        uint32_t off = SW128((uint32_t)(rk * 128 + ce * 2));
        LDMX4T(bh, sbo + OFF_Q0 + half * 8192 + off);
        LDMX4T(bl, sbo + OFF_Q1 + half * 8192 + off);
#pragma unroll
        for (int mt = 0; mt < 2; mt++)
#pragma unroll
            for (int sub = 0; sub < 2; sub++) {
                float* cc = acc[mt][pr * 2 + sub];
                mma_bf16(cc, ah[mt], bh[sub * 2], bh[sub * 2 + 1]);
                mma_bf16(cc, al[mt], bh[sub * 2], bh[sub * 2 + 1]);
                mma_bf16(cc, ah[mt], bl[sub * 2], bl[sub * 2 + 1]);
            }
    }
}

// convert+store 4 H float4s (k = (i0+i)*8+w, e-local = lane*4) into Q tiles
__device__ __forceinline__ void g1_stsA(char* base, const float4* pa, int i0,
                                        int w, int lane) {
    int hh = lane >> 4;
    int el = (lane & 15) * 4;
#pragma unroll
    for (int i = 0; i < 4; i++) {
        int k = (i0 + i) * 8 + w;
        uint2 hi, lo;
        cvt_pair(pa[i], hi, lo);
        uint32_t off = SW128((uint32_t)(k * 128 + el * 2));
        *(uint2*)(base + OFF_Q0 + hh * 8192 + off) = hi;
        *(uint2*)(base + OFF_Q1 + hh * 8192 + off) = lo;
    }
}

__global__ void __launch_bounds__(256, 2)
gemm1_kernel(const float* __restrict__ H) {
    extern __shared__ char smem[];
    const uint32_t sb = smem_u32(smem);
    const int t = threadIdx.x;
    const int lane = t & 31, w = t >> 5;
    const int e0 = blockIdx.x * 128;
    const int c_begin = blockIdx.y * CPS1;
    int c_end = c_begin + CPS1;
    if (c_end > NCH1) c_end = NCH1;
    const int nch = c_end - c_begin;

    const int wf = w >> 2;
    const int we = w & 3;
    const int half = we >> 1;
    const int ebl = (we & 1) * 32;

    const int eA = e0 + lane * 4;
    const bool eok = (eA < E_);
    const int fB = t >> 2;

    float acc[2][4][4];
#pragma unroll
    for (int a = 0; a < 2; a++)
#pragma unroll
        for (int b = 0; b < 4; b++)
#pragma unroll
            for (int q = 0; q < 4; q++) acc[a][b][q] = 0.0f;

    // prologue: chunk 0 -> buf 0
    {
        const int n0 = c_begin * 64;
        float4 pa[8];
#pragma unroll
        for (int i = 0; i < 8; i++) {
            int n = n0 + i * 8 + w;
            pa[i] = (n < N_ && eok) ? *(const float4*)(H + (size_t)n * E_ + eA)
                                    : make_float4(0.f, 0.f, 0.f, 0.f);
        }
        g1_stsA(smem, pa, 0, w, lane);
        g1_stsA(smem, pa + 4, 4, w, lane);
#pragma unroll
        for (int j = 0; j < 2; j++) {
            int sg = (t & 3) + j * 4;
            size_t g = (size_t)fB * NPAD + n0 + sg * 8;
            uint32_t off = SW128((uint32_t)(fB * 128 + sg * 16));
            *(uint4*)(smem + OFF_P0 + off) = *(const uint4*)(g_XsTh + g);
            *(uint4*)(smem + OFF_P1 + off) = *(const uint4*)(g_XsTl + g);
        }
    }
    __syncthreads();

    for (int c = 0; c < nch; c++) {
        const int buf = c & 1;
        const uint32_t sbo = sb + buf * BUFSTRIDE;
        char* nbase = smem + (buf ^ 1) * BUFSTRIDE;
        const bool have = (c + 1 < nch);
        const int n1 = (c_begin + c + 1) * 64;

        uint4 pbh[2], pbl[2];
        if (have) {
#pragma unroll
            for (int j = 0; j < 2; j++) {
                int sg = (t & 3) + j * 4;
                size_t g = (size_t)fB * NPAD + n1 + sg * 8;
                pbh[j] = *(const uint4*)(g_XsTh + g);
                pbl[j] = *(const uint4*)(g_XsTl + g);
            }
        }
        g1_ks(sbo, 0, wf, half, ebl, lane, acc);

        float4 pa1[4];
        if (have) {
#pragma unroll
            for (int i = 0; i < 4; i++) {
                int n = n1 + i * 8 + w;
                pa1[i] = (n < N_ && eok) ? *(const float4*)(H + (size_t)n * E_ + eA)
                                         : make_float4(0.f, 0.f, 0.f, 0.f);
            }
        }
        g1_ks(sbo, 1, wf, half, ebl, lane, acc);

        float4 pa2[4];
        if (have) {
#pragma unroll
            for (int i = 0; i < 4; i++) {
                int n = n1 + (i + 4) * 8 + w;
                pa2[i] = (n < N_ && eok) ? *(const float4*)(H + (size_t)n * E_ + eA)
                                         : make_float4(0.f, 0.f, 0.f, 0.f);
            }
        }
        g1_ks(sbo, 2, wf, half, ebl, lane, acc);
        if (have) g1_stsA(nbase, pa1, 0, w, lane);
        g1_ks(sbo, 3, wf, half, ebl, lane, acc);
        if (have) {
            g1_stsA(nbase, pa2, 4, w, lane);
#pragma unroll
            for (int j = 0; j < 2; j++) {
                int sg = (t & 3) + j * 4;
                uint32_t off = SW128((uint32_t)(fB * 128 + sg * 16));
                *(uint4*)(nbase + OFF_P0 + off) = pbh[j];
                *(uint4*)(nbase + OFF_P1 + off) = pbl[j];
            }
        }
        __syncthreads();
    }

    // epilogue: atomic accumulate into g_YT [f][e]
#pragma unroll
    for (int mt = 0; mt < 2; mt++) {
        int f = wf * 32 + mt * 16 + (lane >> 2);
#pragma unroll
        for (int q = 0; q < 4; q++) {
            int e = e0 + we * 32 + q * 8 + (lane & 3) * 2;
            if (e < E_) {
                atomicAdd(&g_YT[(size_t)f * E_ + e], acc[mt][q][0]);
                atomicAdd(&g_YT[(size_t)f * E_ + e + 1], acc[mt][q][1]);
                atomicAdd(&g_YT[(size_t)(f + 8) * E_ + e], acc[mt][q][2]);
                atomicAdd(&g_YT[(size_t)(f + 8) * E_ + e + 1], acc[mt][q][3]);
            }
        }
    }
}

// ============================================================================
// GEMM2: Z[N,64] += D_v^{-1/2} · H[N,E] · Yd   (split-K=3, atomic epilogue)
// per-buf: P0/P1 = YdT hi/lo [64f][64k], Q0/Q1 = H hi/lo [128n][64k].
// ============================================================================
__device__ __forceinline__ void g2_ks(uint32_t sbo, int ks, int wn, int wfc,
                                      int lane, float acc[2][4][4]) {
    uint32_t ah[2][4], al[2][4];
#pragma unroll
    for (int mt = 0; mt < 2; mt++) {
        int rn = wn * 32 + mt * 16 + (lane & 15);
        uint32_t off = SW128((uint32_t)(rn * 128 + (ks * 16 + (lane >> 4) * 8) * 2));
        LDMX4(ah[mt], sbo + OFF_Q0 + off);
        LDMX4(al[mt], sbo + OFF_Q1 + off);
    }
#pragma unroll
    for (int nt = 0; nt < 2; nt++) {
        uint32_t bh[4], bl[4];
        int fr = wfc * 32 + nt * 16 + (lane >> 4) * 8 + (lane & 7);
        int kb8 = ((lane >> 3) & 1) * 8;
        uint32_t off = SW128((uint32_t)(fr * 128 + (ks * 16 + kb8) * 2));
        LDMX4(bh, sbo + OFF_P0 + off);
        LDMX4(bl, sbo + OFF_P1 + off);
#pragma unroll
        for (int mt = 0; mt < 2; mt++)
#pragma unroll
            for (int sub = 0; sub < 2; sub++) {
                float* cc = acc[mt][nt * 2 + sub];
                mma_bf16(cc, ah[mt], bh[sub * 2], bh[sub * 2 + 1]);
                mma_bf16(cc, al[mt], bh[sub * 2], bh[sub * 2 + 1]);
                mma_bf16(cc, ah[mt], bl[sub * 2], bl[sub * 2 + 1]);
            }
    }
}

// convert+store 4 H float4s (r = (i0+i)*16 + t>>4, k-local = (t&15)*4)
__device__ __forceinline__ void g2_stsA(char* base, const float4* pa, int i0, int t) {
    int kl = (t & 15) * 4;
#pragma unroll
    for (int i = 0; i < 4; i++) {
        int r = (i0 + i) * 16 + (t >> 4);
        uint2 hi, lo;
        cvt_pair(pa[i], hi, lo);
        uint32_t off = SW128((uint32_t)(r * 128 + kl * 2));
        *(uint2*)(base + OFF_Q0 + off) = hi;
        *(uint2*)(base + OFF_Q1 + off) = lo;
    }
}

__global__ void __launch_bounds__(256, 2)
gemm2_kernel(const float* __restrict__ H, float* __restrict__ Z) {
    extern __shared__ char smem[];
    const uint32_t sb = smem_u32(smem);
    const int t = threadIdx.x;
    const int lane = t & 31, w = t >> 5;
    const int n0 = blockIdx.x * 128;
    const int c_begin = blockIdx.y * CPS2;
    int c_end = c_begin + CPS2;
    if (c_end > NCH2) c_end = NCH2;
    const int nch = c_end - c_begin;

    const int wn = w >> 1;
    const int wfc = w & 1;
    const int fB = t >> 2;
    const int rA = t >> 4;       // row sub-index for A loads
    const int kA = (t & 15) * 4; // k sub-index for A loads

    float acc[2][4][4];
#pragma unroll
    for (int a = 0; a < 2; a++)
#pragma unroll
        for (int b = 0; b < 4; b++)
#pragma unroll
            for (int q = 0; q < 4; q++) acc[a][b][q] = 0.0f;

    // prologue: chunk 0 -> buf 0
    {
        const int k0 = c_begin * 64;
        float4 pa[8];
#pragma unroll
        for (int i = 0; i < 8; i++) {
            int n = n0 + i * 16 + rA;
            pa[i] = (n < N_) ? *(const float4*)(H + (size_t)n * E_ + k0 + kA)
                             : make_float4(0.f, 0.f, 0.f, 0.f);
        }
        g2_stsA(smem, pa, 0, t);
        g2_stsA(smem, pa + 4, 4, t);
#pragma unroll
        for (int j = 0; j < 2; j++) {
            int sg = (t & 3) + j * 4;
            size_t g = (size_t)fB * E_ + k0 + sg * 8;
            uint32_t off = SW128((uint32_t)(fB * 128 + sg * 16));
            *(uint4*)(smem + OFF_P0 + off) = *(const uint4*)(g_YdTh + g);
            *(uint4*)(smem + OFF_P1 + off) = *(const uint4*)(g_YdTl + g);
        }
    }
    __syncthreads();

    for (int c = 0; c < nch; c++) {
        const int buf = c & 1;
        const uint32_t sbo = sb + buf * BUFSTRIDE;
        char* nbase = smem + (buf ^ 1) * BUFSTRIDE;
        const bool have = (c + 1 < nch);
        const int k1 = (c_begin + c + 1) * 64;

        uint4 pbh[2], pbl[2];
        if (have) {
#pragma unroll
            for (int j = 0; j < 2; j++) {
                int sg = (t & 3) + j * 4;
                size_t g = (size_t)fB * E_ + k1 + sg * 8;
                pbh[j] = *(const uint4*)(g_YdTh + g);
                pbl[j] = *(const uint4*)(g_YdTl + g);
            }
        }
        g2_ks(sbo, 0, wn, wfc, lane, acc);

        float4 pa1[4];
        if (have) {
#pragma unroll
            for (int i = 0; i < 4; i++) {
                int n = n0 + i * 16 + rA;
                pa1[i] = (n < N_) ? *(const float4*)(H + (size_t)n * E_ + k1 + kA)
                                  : make_float4(0.f, 0.f, 0.f, 0.f);
            }
        }
        g2_ks(sbo, 1, wn, wfc, lane, acc);

        float4 pa2[4];
        if (have) {
#pragma unroll
            for (int i = 0; i < 4; i++) {
                int n = n0 + (i + 4) * 16 + rA;
                pa2[i] = (n < N_) ? *(const float4*)(H + (size_t)n * E_ + k1 + kA)
                                  : make_float4(0.f, 0.f, 0.f, 0.f);
            }
        }
        g2_ks(sbo, 2, wn, wfc, lane, acc);
        if (have) g2_stsA(nbase, pa1, 0, t);
        g2_ks(sbo, 3, wn, wfc, lane, acc);
        if (have) {
            g2_stsA(nbase, pa2, 4, t);
#pragma unroll
            for (int j = 0; j < 2; j++) {
                int sg = (t & 3) + j * 4;
                uint32_t off = SW128((uint32_t)(fB * 128 + sg * 16));
                *(uint4*)(nbase + OFF_P0 + off) = pbh[j];
                *(uint4*)(nbase + OFF_P1 + off) = pbl[j];
            }
        }
        __syncthreads();
    }

    // epilogue: scale partials by rsqrt(d_v) and atomically accumulate
#pragma unroll
    for (int mt = 0; mt < 2; mt++) {
        int n_lo = n0 + wn * 32 + mt * 16 + (lane >> 2);
        int n_hi = n_lo + 8;
        float s_lo = (n_lo < N_) ? rsqrtf(g_dv[n_lo] + EPS) : 0.0f;
        float s_hi = (n_hi < N_) ? rsqrtf(g_dv[n_hi] + EPS) : 0.0f;
#pragma unroll
        for (int q = 0; q < 4; q++) {
            int f = wfc * 32 + q * 8 + (lane & 3) * 2;
            if (n_lo < N_) {
                atomicAdd(&Z[(size_t)n_lo * 64 + f], acc[mt][q][0] * s_lo);
                atomicAdd(&Z[(size_t)n_lo * 64 + f + 1], acc[mt][q][1] * s_lo);
            }
            if (n_hi < N_) {
                atomicAdd(&Z[(size_t)n_hi * 64 + f], acc[mt][q][2] * s_hi);
                atomicAdd(&Z[(size_t)n_hi * 64 + f + 1], acc[mt][q][3] * s_hi);
            }
        }
    }
}

// ---------------------------------------------------------------------------
extern "C" void kernel_launch(void* const* d_in, const int* in_sizes, int n_in,
                              void* d_out, int out_size) {
    const float* H = (const float*)d_in[0];  // [N_, E_] fp32
    const float* X = (const float*)d_in[1];  // [N_, F_] fp32
    float* Z = (float*)d_out;                // [N_, F_] fp32

    cudaFuncSetAttribute(gemm1_kernel, cudaFuncAttributeMaxDynamicSharedMemorySize, G_TOTAL);
    cudaFuncSetAttribute(gemm2_kernel, cudaFuncAttributeMaxDynamicSharedMemorySize, G_TOTAL);

    zero_scratch<<<(N_ * F_ + 255) / 256, 256>>>(Z);
    degrees_kernel<<<444, 256>>>(H);
    scale_x_t<<<(NPAD + 127) / 128, 256>>>(X);
    gemm1_kernel<<<dim3(ETILES1, SPLIT1), 256, G_TOTAL>>>(H);
    scale_y_t<<<(64 * E_ + 255) / 256, 256>>>();
    gemm2_kernel<<<dim3(NTILES2, SPLIT2), 256, G_TOTAL>>>(H, Z);
}